// round 1
// baseline (speedup 1.0000x reference)
#include <cuda_runtime.h>
#include <cuda_bf16.h>

// out[b,i,o] = relu( sum_f s[b,i,f] * W[f,o] + bias[o] * deg[b,i] )
// where s[b,i,f] = sum_j adj[b,i,j] * concat(sf1,sf2)[b,i,j,f]
//       deg[b,i] = sum_j adj[b,i,j]
//
// B=16, M=128, F_IN_EACH=64, F=128 (concat), F_OUT=128.
// One block per (b,i) row: ROWS = B*M = 2048.

#define ROWS 2048
#define MJ   128      // neighbor count (j)
#define FE   64       // features per input tensor
#define FC   128      // concatenated features
#define FO   128      // output features

__global__ __launch_bounds__(256, 4)
void gcn_fused_kernel(const float* __restrict__ sf1,
                      const float* __restrict__ sf2,
                      const float* __restrict__ adj,
                      const float* __restrict__ W,
                      const float* __restrict__ bias,
                      float* __restrict__ out)
{
    __shared__ float  s_adj[MJ];
    __shared__ float  s_sm[FC];
    __shared__ float4 red4[256];   // aliased as float[1024] for phase-2 reduction
    __shared__ float  s_deg;

    float* redf = reinterpret_cast<float*>(red4);

    const int row = blockIdx.x;    // b*128 + i
    const int t   = threadIdx.x;

    // ---- Phase 1: adjacency row -> smem ----
    if (t < MJ) s_adj[t] = adj[(size_t)row * MJ + t];
    __syncthreads();

    // degree (warp 0)
    if (t < 32) {
        float d = s_adj[t] + s_adj[t + 32] + s_adj[t + 64] + s_adj[t + 96];
        #pragma unroll
        for (int off = 16; off > 0; off >>= 1)
            d += __shfl_down_sync(0xffffffffu, d, off);
        if (t == 0) s_deg = d;
    }

    // ---- Phase 2: masked reduction over j (skip zero-adjacency rows) ----
    // thread t: channel c = t & 127 (c<64 -> sf1[c], c>=64 -> sf2[c-64]),
    //           j-parity p = t >> 7.  Branch on s_adj[j] is warp-uniform.
    {
        const int c = t & (FC - 1);
        const int p = t >> 7;
        const float* base = ((c < FE) ? sf1 : sf2)
                          + (size_t)row * MJ * FE + (c & (FE - 1));
        float acc = 0.0f;
        #pragma unroll 4
        for (int j = p; j < MJ; j += 2) {
            float a = s_adj[j];
            if (a != 0.0f) {
                acc += a * __ldcs(base + (size_t)j * FE);
            }
        }
        redf[t] = acc;
    }
    __syncthreads();
    if (t < FC) s_sm[t] = redf[t] + redf[t + FC];
    __syncthreads();

    // ---- Phase 3: s (1x128) @ W (128x128), split-K over 8 groups ----
    // thread t: output quad oq = t & 31 (4 outputs via float4),
    //           k-slice  kq = t >> 5 (16 f-values each).
    {
        const int oq = t & 31;
        const int kq = t >> 5;
        const float4* W4 = reinterpret_cast<const float4*>(W);
        float4 acc = make_float4(0.f, 0.f, 0.f, 0.f);
        const int f0 = kq * 16;
        #pragma unroll
        for (int k = 0; k < 16; ++k) {
            const int f = f0 + k;
            const float s  = s_sm[f];           // warp-broadcast LDS
            const float4 w = W4[f * 32 + oq];   // coalesced 512B/warp
            acc.x += s * w.x;
            acc.y += s * w.y;
            acc.z += s * w.z;
            acc.w += s * w.w;
        }
        red4[t] = acc;
    }
    __syncthreads();

    // ---- Final combine + bias*deg + relu + store ----
    if (t < 32) {
        float4 r = red4[t];
        #pragma unroll
        for (int k = 1; k < 8; ++k) {
            float4 q = red4[t + 32 * k];
            r.x += q.x; r.y += q.y; r.z += q.z; r.w += q.w;
        }
        const float4 bb = reinterpret_cast<const float4*>(bias)[t];
        const float  d  = s_deg;
        float4 o4;
        o4.x = fmaxf(r.x + bb.x * d, 0.0f);
        o4.y = fmaxf(r.y + bb.y * d, 0.0f);
        o4.z = fmaxf(r.z + bb.z * d, 0.0f);
        o4.w = fmaxf(r.w + bb.w * d, 0.0f);
        reinterpret_cast<float4*>(out)[(size_t)row * 32 + t] = o4;
    }
}

extern "C" void kernel_launch(void* const* d_in, const int* in_sizes, int n_in,
                              void* d_out, int out_size)
{
    const float* sf1  = (const float*)d_in[0];  // (16,128,128,64)
    const float* sf2  = (const float*)d_in[1];  // (16,128,128,64)
    const float* adj  = (const float*)d_in[2];  // (16,128,128)
    const float* W    = (const float*)d_in[3];  // (128,128)
    const float* bias = (const float*)d_in[4];  // (128,)
    float* out = (float*)d_out;                 // (16,128,128)

    gcn_fused_kernel<<<ROWS, 256>>>(sf1, sf2, adj, W, bias, out);
}

// round 2
// speedup vs baseline: 1.4419x; 1.4419x over previous
#include <cuda_runtime.h>
#include <cuda_bf16.h>

// out[b,i,o] = relu( sum_f s[b,i,f] * W[f,o] + bias[o] * deg[b,i] )
// where s[b,i,f] = sum_j adj[b,i,j] * concat(sf1,sf2)[b,i,j,f]
//       deg[b,i] = sum_j adj[b,i,j]
//
// B=16, M=128: one block per (b,i) row, ROWS = 2048 blocks, 256 threads.
// Round 2: deterministic compaction of nonzero adjacency entries, then a
// branch-free gather loop unrolled x4 (MLP=4) to hide DRAM latency.

#define ROWS 2048
#define MJ   128      // neighbor count (j)
#define FE   64       // features per input tensor
#define FC   128      // concatenated features
#define FO   128      // output features

__global__ __launch_bounds__(256, 4)
void gcn_fused_kernel(const float* __restrict__ sf1,
                      const float* __restrict__ sf2,
                      const float* __restrict__ adj,
                      const float* __restrict__ W,
                      const float* __restrict__ bias,
                      float* __restrict__ out)
{
    __shared__ float  s_adj[MJ];
    __shared__ float2 s_comp[MJ];   // (adj value, j index as int bits), compacted
    __shared__ int    s_woff[4];    // per-warp exclusive offsets
    __shared__ int    s_nnz;
    __shared__ float  s_sm[FC];
    __shared__ float4 red4[256];
    __shared__ float  s_deg;

    float* redf = reinterpret_cast<float*>(red4);

    const int row = blockIdx.x;    // b*128 + i
    const int t   = threadIdx.x;

    // ---- Phase 1a: adjacency row -> smem ----
    if (t < MJ) s_adj[t] = adj[(size_t)row * MJ + t];
    __syncthreads();

    // ---- Phase 1b: per-warp nonzero counts (warps 0..3) + degree (warp 7) ----
    float a_t = 0.0f;
    unsigned bal = 0;
    if (t < MJ) {
        a_t = s_adj[t];
        bal = __ballot_sync(0xffffffffu, a_t != 0.0f);
        if ((t & 31) == 0) s_woff[t >> 5] = __popc(bal);
    }
    if (t >= 224) {  // warp 7 computes degree
        const int l = t - 224;
        float d = s_adj[l] + s_adj[l + 32] + s_adj[l + 64] + s_adj[l + 96];
        #pragma unroll
        for (int off = 16; off > 0; off >>= 1)
            d += __shfl_down_sync(0xffffffffu, d, off);
        if (l == 0) s_deg = d;
    }
    __syncthreads();

    // ---- Phase 1c: exclusive prefix over 4 warp counts (thread 0) ----
    if (t == 0) {
        int c0 = s_woff[0], c1 = s_woff[1], c2 = s_woff[2], c3 = s_woff[3];
        s_woff[0] = 0;
        s_woff[1] = c0;
        s_woff[2] = c0 + c1;
        s_woff[3] = c0 + c1 + c2;
        s_nnz     = c0 + c1 + c2 + c3;
    }
    __syncthreads();

    // ---- Phase 1d: deterministic scatter of compacted entries ----
    if (t < MJ && a_t != 0.0f) {
        const int w = t >> 5, l = t & 31;
        const int pos = s_woff[w] + __popc(bal & ((1u << l) - 1u));
        s_comp[pos] = make_float2(a_t, __int_as_float(t));
    }
    __syncthreads();

    // ---- Phase 2: branch-free masked gather-reduce over compacted list ----
    // thread t: channel c = t & 127 (c<64 -> sf1, else sf2), parity p = t>>7.
    {
        const int nnz = s_nnz;
        const int c = t & (FC - 1);
        const int p = t >> 7;
        const float* base = ((c < FE) ? sf1 : sf2)
                          + (size_t)row * MJ * FE + (c & (FE - 1));
        float acc0 = 0.f, acc1 = 0.f, acc2 = 0.f, acc3 = 0.f;
        int k = p;
        // main loop: 4 independent loads in flight per thread
        for (; k + 6 < nnz; k += 8) {
            const float2 e0 = s_comp[k];
            const float2 e1 = s_comp[k + 2];
            const float2 e2 = s_comp[k + 4];
            const float2 e3 = s_comp[k + 6];
            const float v0 = __ldcs(base + (size_t)__float_as_int(e0.y) * FE);
            const float v1 = __ldcs(base + (size_t)__float_as_int(e1.y) * FE);
            const float v2 = __ldcs(base + (size_t)__float_as_int(e2.y) * FE);
            const float v3 = __ldcs(base + (size_t)__float_as_int(e3.y) * FE);
            acc0 += e0.x * v0;
            acc1 += e1.x * v1;
            acc2 += e2.x * v2;
            acc3 += e3.x * v3;
        }
        for (; k < nnz; k += 2) {
            const float2 e = s_comp[k];
            acc0 += e.x * __ldcs(base + (size_t)__float_as_int(e.y) * FE);
        }
        redf[t] = (acc0 + acc1) + (acc2 + acc3);
    }
    __syncthreads();
    if (t < FC) s_sm[t] = redf[t] + redf[t + FC];
    __syncthreads();

    // ---- Phase 3: s (1x128) @ W (128x128), split-K over 8 groups ----
    {
        const int oq = t & 31;        // output quad (4 outputs via float4)
        const int kq = t >> 5;        // k-slice (16 f-values)
        const float4* W4 = reinterpret_cast<const float4*>(W);
        float4 acc = make_float4(0.f, 0.f, 0.f, 0.f);
        const int f0 = kq * 16;
        #pragma unroll
        for (int k = 0; k < 16; ++k) {
            const int f = f0 + k;
            const float s  = s_sm[f];           // warp-broadcast LDS
            const float4 w = W4[f * 32 + oq];   // coalesced 512B/warp, L2-resident
            acc.x += s * w.x;
            acc.y += s * w.y;
            acc.z += s * w.z;
            acc.w += s * w.w;
        }
        red4[t] = acc;
    }
    __syncthreads();

    // ---- Final combine + bias*deg + relu + store ----
    if (t < 32) {
        float4 r = red4[t];
        #pragma unroll
        for (int k = 1; k < 8; ++k) {
            float4 q = red4[t + 32 * k];
            r.x += q.x; r.y += q.y; r.z += q.z; r.w += q.w;
        }
        const float4 bb = reinterpret_cast<const float4*>(bias)[t];
        const float  d  = s_deg;
        float4 o4;
        o4.x = fmaxf(r.x + bb.x * d, 0.0f);
        o4.y = fmaxf(r.y + bb.y * d, 0.0f);
        o4.z = fmaxf(r.z + bb.z * d, 0.0f);
        o4.w = fmaxf(r.w + bb.w * d, 0.0f);
        reinterpret_cast<float4*>(out)[(size_t)row * 32 + t] = o4;
    }
}

extern "C" void kernel_launch(void* const* d_in, const int* in_sizes, int n_in,
                              void* d_out, int out_size)
{
    const float* sf1  = (const float*)d_in[0];  // (16,128,128,64)
    const float* sf2  = (const float*)d_in[1];  // (16,128,128,64)
    const float* adj  = (const float*)d_in[2];  // (16,128,128)
    const float* W    = (const float*)d_in[3];  // (128,128)
    const float* bias = (const float*)d_in[4];  // (128,)
    float* out = (float*)d_out;                 // (16,128,128)

    gcn_fused_kernel<<<ROWS, 256>>>(sf1, sf2, adj, W, bias, out);
}

// round 3
// speedup vs baseline: 1.5975x; 1.1079x over previous
#include <cuda_runtime.h>
#include <cuda_bf16.h>

// out[b,i,o] = relu( sum_f s[b,i,f] * W[f,o] + bias[o] * deg[b,i] )
// where s[b,i,f] = sum_j adj[b,i,j] * concat(sf1,sf2)[b,i,j,f]
//       deg[b,i] = sum_j adj[b,i,j]
//
// One block per (b,i) row: 2048 blocks x 256 threads.
// Round 3: warp-per-j-entry float4 gather (64B in flight per thread).

#define ROWS 2048
#define MJ   128      // neighbor count (j)
#define FE   64       // features per input tensor
#define FC   128      // concatenated features
#define FO   128      // output features

__global__ __launch_bounds__(256, 6)
void gcn_fused_kernel(const float* __restrict__ sf1,
                      const float* __restrict__ sf2,
                      const float* __restrict__ adj,
                      const float* __restrict__ W,
                      const float* __restrict__ bias,
                      float* __restrict__ out)
{
    __shared__ float2 s_comp[MJ];   // compacted (adj value, j index bits)
    __shared__ int    s_cnt[4];
    __shared__ float  s_dsum[4];
    __shared__ int    s_woff[4];
    __shared__ int    s_nnz;
    __shared__ float  s_deg;
    __shared__ float  s_sm[FC];
    __shared__ float4 red4[256];

    float* redf = reinterpret_cast<float*>(red4);

    const int row  = blockIdx.x;   // b*128 + i
    const int t    = threadIdx.x;
    const int w    = t >> 5;
    const int lane = t & 31;

    // ---- Phase 1: adj row -> registers, ballot-compact metadata ----
    float a = 0.0f;
    unsigned bal = 0;
    if (t < MJ) {
        a   = __ldg(adj + (size_t)row * MJ + t);
        bal = __ballot_sync(0xffffffffu, a != 0.0f);
        float d = a;
        #pragma unroll
        for (int off = 16; off > 0; off >>= 1)
            d += __shfl_down_sync(0xffffffffu, d, off);
        if (lane == 0) { s_cnt[w] = __popc(bal); s_dsum[w] = d; }
    }
    __syncthreads();

    if (t == 0) {
        const int c0 = s_cnt[0], c1 = s_cnt[1], c2 = s_cnt[2], c3 = s_cnt[3];
        s_woff[0] = 0;
        s_woff[1] = c0;
        s_woff[2] = c0 + c1;
        s_woff[3] = c0 + c1 + c2;
        s_nnz     = c0 + c1 + c2 + c3;
        s_deg     = s_dsum[0] + s_dsum[1] + s_dsum[2] + s_dsum[3];
    }
    __syncthreads();

    if (t < MJ && a != 0.0f) {
        const int pos = s_woff[w] + __popc(bal & ((1u << lane) - 1u));
        s_comp[pos] = make_float2(a, __int_as_float(t));
    }
    __syncthreads();

    // ---- Phase 2: warp-per-entry float4 gather ----
    // Warp w processes entries k = w, w+8, w+16, ...  For each entry,
    // lanes 0-15 load the 64-float sf1 row (float4 each), lanes 16-31 sf2.
    // Thread's channel quad = lane*4 .. lane*4+3 (continuous 0..127).
    {
        const int nnz = s_nnz;
        const float* base = ((lane < 16) ? sf1 : sf2)
                          + (size_t)row * MJ * FE + (lane & 15) * 4;
        float4 acc = make_float4(0.f, 0.f, 0.f, 0.f);
        int k = w;
        for (; k + 24 < nnz; k += 32) {   // 4 independent 16B loads in flight
            const float2 e0 = s_comp[k];
            const float2 e1 = s_comp[k + 8];
            const float2 e2 = s_comp[k + 16];
            const float2 e3 = s_comp[k + 24];
            const float4 v0 = __ldcs(reinterpret_cast<const float4*>(
                                  base + (size_t)__float_as_int(e0.y) * FE));
            const float4 v1 = __ldcs(reinterpret_cast<const float4*>(
                                  base + (size_t)__float_as_int(e1.y) * FE));
            const float4 v2 = __ldcs(reinterpret_cast<const float4*>(
                                  base + (size_t)__float_as_int(e2.y) * FE));
            const float4 v3 = __ldcs(reinterpret_cast<const float4*>(
                                  base + (size_t)__float_as_int(e3.y) * FE));
            acc.x += e0.x * v0.x; acc.y += e0.x * v0.y;
            acc.z += e0.x * v0.z; acc.w += e0.x * v0.w;
            acc.x += e1.x * v1.x; acc.y += e1.x * v1.y;
            acc.z += e1.x * v1.z; acc.w += e1.x * v1.w;
            acc.x += e2.x * v2.x; acc.y += e2.x * v2.y;
            acc.z += e2.x * v2.z; acc.w += e2.x * v2.w;
            acc.x += e3.x * v3.x; acc.y += e3.x * v3.y;
            acc.z += e3.x * v3.z; acc.w += e3.x * v3.w;
        }
        for (; k < nnz; k += 8) {
            const float2 e = s_comp[k];
            const float4 v = __ldcs(reinterpret_cast<const float4*>(
                                 base + (size_t)__float_as_int(e.y) * FE));
            acc.x += e.x * v.x; acc.y += e.x * v.y;
            acc.z += e.x * v.z; acc.w += e.x * v.w;
        }
        red4[t] = acc;   // float index w*128 + lane*4 + comp = w*128 + channel
    }
    __syncthreads();

    // combine 8 warp-partials per channel
    if (t < FC) {
        float s = 0.0f;
        #pragma unroll
        for (int ww = 0; ww < 8; ++ww) s += redf[ww * FC + t];
        s_sm[t] = s;
    }
    __syncthreads();

    // ---- Phase 3: s (1x128) @ W (128x128), split-K over 8 groups ----
    {
        const int oq = t & 31;        // output quad (4 outputs via float4)
        const int kq = t >> 5;        // k-slice (16 f-values)
        const float4* W4 = reinterpret_cast<const float4*>(W);
        float4 acc = make_float4(0.f, 0.f, 0.f, 0.f);
        const int f0 = kq * 16;
        #pragma unroll
        for (int k = 0; k < 16; ++k) {
            const int f = f0 + k;
            const float s  = s_sm[f];           // warp-broadcast LDS
            const float4 wv = W4[f * 32 + oq];  // coalesced, L2-resident
            acc.x += s * wv.x;
            acc.y += s * wv.y;
            acc.z += s * wv.z;
            acc.w += s * wv.w;
        }
        red4[t] = acc;
    }
    __syncthreads();

    // ---- Final combine + bias*deg + relu + store ----
    if (t < 32) {
        float4 r = red4[t];
        #pragma unroll
        for (int k = 1; k < 8; ++k) {
            float4 q = red4[t + 32 * k];
            r.x += q.x; r.y += q.y; r.z += q.z; r.w += q.w;
        }
        const float4 bb = reinterpret_cast<const float4*>(bias)[t];
        const float  d  = s_deg;
        float4 o4;
        o4.x = fmaxf(r.x + bb.x * d, 0.0f);
        o4.y = fmaxf(r.y + bb.y * d, 0.0f);
        o4.z = fmaxf(r.z + bb.z * d, 0.0f);
        o4.w = fmaxf(r.w + bb.w * d, 0.0f);
        reinterpret_cast<float4*>(out)[(size_t)row * 32 + t] = o4;
    }
}

extern "C" void kernel_launch(void* const* d_in, const int* in_sizes, int n_in,
                              void* d_out, int out_size)
{
    const float* sf1  = (const float*)d_in[0];  // (16,128,128,64)
    const float* sf2  = (const float*)d_in[1];  // (16,128,128,64)
    const float* adj  = (const float*)d_in[2];  // (16,128,128)
    const float* W    = (const float*)d_in[3];  // (128,128)
    const float* bias = (const float*)d_in[4];  // (128,)
    float* out = (float*)d_out;                 // (16,128,128)

    gcn_fused_kernel<<<ROWS, 256>>>(sf1, sf2, adj, W, bias, out);
}